// round 6
// baseline (speedup 1.0000x reference)
#include <cuda_runtime.h>

// SimpleTP: FullTensorProduct('1x1o','1x1o') of frac with itself, summed over N.
// Reduces to 6 quadratic moments s_ij = sum_n frac[n,i]*frac[n,j] (i<=j), then a
// fixed linear map to 9 outputs (cross part is identically 0).
// Streaming via smem staging: dense coalesced LDG.128 -> smem -> conflict-free
// LDS.128 row reads. Single kernel, threadfence last-block epilogue.

#define BLK 256
#define GRID_MAIN 1184          // ~8 blocks/SM
#define NACC 6
#define TILE_F4 (3 * BLK)       // 768 float4 = 3072 floats = 1024 rows = 12 KB

// Scratch partials, SoA: g_part[k*GRID_MAIN + b]
__device__ float g_part[NACC * GRID_MAIN];
__device__ unsigned int g_count = 0;

__device__ __forceinline__ void acc3(float a, float b, float c,
                                     float& s00, float& s11, float& s22,
                                     float& s01, float& s02, float& s12) {
    s00 = fmaf(a, a, s00);
    s11 = fmaf(b, b, s11);
    s22 = fmaf(c, c, s22);
    s01 = fmaf(a, b, s01);
    s02 = fmaf(a, c, s02);
    s12 = fmaf(b, c, s12);
}

__device__ __forceinline__ void acc_vec3(const float4& v0, const float4& v1, const float4& v2,
                                         float& s00, float& s11, float& s22,
                                         float& s01, float& s02, float& s12) {
    acc3(v0.x, v0.y, v0.z, s00, s11, s22, s01, s02, s12);
    acc3(v0.w, v1.x, v1.y, s00, s11, s22, s01, s02, s12);
    acc3(v1.z, v1.w, v2.x, s00, s11, s22, s01, s02, s12);
    acc3(v2.y, v2.z, v2.w, s00, s11, s22, s01, s02, s12);
}

__global__ __launch_bounds__(BLK) void tp_kernel(const float* __restrict__ in,
                                                 int total_floats,
                                                 float* __restrict__ out) {
    __shared__ float4 tile[TILE_F4];           // 12 KB staging buffer
    const float4* __restrict__ in4 = (const float4*)in;
    const int num_tiles = total_floats / (TILE_F4 * 4);

    float s00 = 0.f, s11 = 0.f, s22 = 0.f, s01 = 0.f, s02 = 0.f, s12 = 0.f;

    const int tid = threadIdx.x;
    int t = blockIdx.x;

    // prologue: issue first tile's loads
    float4 r0, r1, r2;
    if (t < num_tiles) {
        const float4* src = in4 + (size_t)t * TILE_F4;
        r0 = src[tid];
        r1 = src[tid + BLK];
        r2 = src[tid + 2 * BLK];
    }

    while (t < num_tiles) {
        tile[tid]           = r0;
        tile[tid + BLK]     = r1;
        tile[tid + 2 * BLK] = r2;
        __syncthreads();

        // issue NEXT tile's loads before computing (overlap DRAM latency)
        int tn = t + gridDim.x;
        if (tn < num_tiles) {
            const float4* src = in4 + (size_t)tn * TILE_F4;
            r0 = src[tid];
            r1 = src[tid + BLK];
            r2 = src[tid + 2 * BLK];
        }

        // each thread: 4 rows = 12 floats from smem (48B stride, conflict-free)
        const float* tf = (const float*)tile;
        float4 a = *(const float4*)(tf + 12 * tid);
        float4 b = *(const float4*)(tf + 12 * tid + 4);
        float4 c = *(const float4*)(tf + 12 * tid + 8);
        acc_vec3(a, b, c, s00, s11, s22, s01, s02, s12);

        __syncthreads();   // before overwriting tile next iteration
        t = tn;
    }

    // warp reduction
    #pragma unroll
    for (int o = 16; o > 0; o >>= 1) {
        s00 += __shfl_down_sync(0xffffffffu, s00, o);
        s11 += __shfl_down_sync(0xffffffffu, s11, o);
        s22 += __shfl_down_sync(0xffffffffu, s22, o);
        s01 += __shfl_down_sync(0xffffffffu, s01, o);
        s02 += __shfl_down_sync(0xffffffffu, s02, o);
        s12 += __shfl_down_sync(0xffffffffu, s12, o);
    }

    __shared__ float sm[NACC][BLK / 32];
    int lane = tid & 31;
    int w = tid >> 5;
    if (lane == 0) {
        sm[0][w] = s00; sm[1][w] = s11; sm[2][w] = s22;
        sm[3][w] = s01; sm[4][w] = s02; sm[5][w] = s12;
    }
    __syncthreads();

    if (tid < NACC) {
        float v = 0.f;
        #pragma unroll
        for (int i = 0; i < BLK / 32; i++) v += sm[tid][i];
        g_part[tid * GRID_MAIN + blockIdx.x] = v;
    }

    // ---- last-block epilogue (threadfence reduction) ----
    __shared__ bool is_last;
    __threadfence();
    if (tid == 0) {
        unsigned int prev = atomicAdd(&g_count, 1u);
        is_last = (prev == (unsigned int)(gridDim.x - 1));
    }
    __syncthreads();
    if (!is_last) return;

    const volatile float* vpart = (const volatile float*)g_part;
    float s[NACC];
    #pragma unroll
    for (int k = 0; k < NACC; k++) s[k] = 0.f;

    for (int b = tid; b < GRID_MAIN; b += BLK) {
        #pragma unroll
        for (int k = 0; k < NACC; k++) s[k] += vpart[k * GRID_MAIN + b];
    }

    // tail rows beyond full tiles, distributed over this block (deterministic)
    {
        int num_rows = total_floats / 3;
        int covered = num_tiles * (TILE_F4 * 4 / 3);   // rows covered by tiles
        for (int r = covered + tid; r < num_rows; r += BLK) {
            float a = in[3 * r + 0], b = in[3 * r + 1], c = in[3 * r + 2];
            s[0] += a * a; s[1] += b * b; s[2] += c * c;
            s[3] += a * b; s[4] += a * c; s[5] += b * c;
        }
    }

    // block reduce (fixed order -> deterministic)
    #pragma unroll
    for (int o = 16; o > 0; o >>= 1) {
        #pragma unroll
        for (int k = 0; k < NACC; k++) s[k] += __shfl_down_sync(0xffffffffu, s[k], o);
    }
    __shared__ float sm2[NACC][BLK / 32];
    if (lane == 0) {
        #pragma unroll
        for (int k = 0; k < NACC; k++) sm2[k][w] = s[k];
    }
    __syncthreads();

    if (tid == 0) {
        float v[NACC];
        #pragma unroll
        for (int k = 0; k < NACC; k++) {
            v[k] = 0.f;
            #pragma unroll
            for (int i = 0; i < BLK / 32; i++) v[k] += sm2[k][i];
        }
        const float s00f = v[0], s11f = v[1], s22f = v[2];
        const float s01f = v[3], s02f = v[4], s12f = v[5];
        const float INV_SQRT3 = 0.57735026918962576f;
        const float SQRT2     = 1.41421356237309505f;
        const float INV_SQRT6 = 0.40824829046386302f;
        const float INV_SQRT2 = 0.70710678118654752f;

        out[0] = (s00f + s11f + s22f) * INV_SQRT3;        // 0e
        out[1] = 0.f;                                     // 1e: cross(x,x)=0
        out[2] = 0.f;
        out[3] = 0.f;
        out[4] = SQRT2 * s02f;                            // 2e m=-2
        out[5] = SQRT2 * s01f;                            // 2e m=-1
        out[6] = (2.f * s11f - s00f - s22f) * INV_SQRT6;  // 2e m=0
        out[7] = SQRT2 * s12f;                            // 2e m=+1
        out[8] = (s22f - s00f) * INV_SQRT2;               // 2e m=+2

        g_count = 0;   // reset for next graph replay
    }
}

extern "C" void kernel_launch(void* const* d_in, const int* in_sizes, int n_in,
                              void* d_out, int out_size) {
    const float* frac = (const float*)d_in[0];
    float* out = (float*)d_out;
    int total_floats = in_sizes[0];          // N*3

    tp_kernel<<<GRID_MAIN, BLK>>>(frac, total_floats, out);
}

// round 7
// speedup vs baseline: 1.0521x; 1.0521x over previous
#include <cuda_runtime.h>

// SimpleTP: FullTensorProduct('1x1o','1x1o') of frac with itself, summed over N.
// Reduces to 6 quadratic moments s_ij = sum_n frac[n,i]*frac[n,j] (i<=j), then a
// fixed linear map to 9 outputs (cross part is identically 0).
// Single kernel: streaming float4 loads + last-block epilogue with exactly ONE
// gpu-scope fence per block (single-publisher pattern).

#define BLK 256
#define GRID_MAIN 1184          // ~8 blocks/SM
#define NACC 6

// Partials: one 32B-aligned record of 8 floats per block (6 used).
__device__ __align__(32) float g_part[GRID_MAIN * 8];
__device__ unsigned int g_count = 0;

__device__ __forceinline__ void acc3(float a, float b, float c,
                                     float& s00, float& s11, float& s22,
                                     float& s01, float& s02, float& s12) {
    s00 = fmaf(a, a, s00);
    s11 = fmaf(b, b, s11);
    s22 = fmaf(c, c, s22);
    s01 = fmaf(a, b, s01);
    s02 = fmaf(a, c, s02);
    s12 = fmaf(b, c, s12);
}

__device__ __forceinline__ void acc_vec3(const float4& v0, const float4& v1, const float4& v2,
                                         float& s00, float& s11, float& s22,
                                         float& s01, float& s02, float& s12) {
    acc3(v0.x, v0.y, v0.z, s00, s11, s22, s01, s02, s12);
    acc3(v0.w, v1.x, v1.y, s00, s11, s22, s01, s02, s12);
    acc3(v1.z, v1.w, v2.x, s00, s11, s22, s01, s02, s12);
    acc3(v2.y, v2.z, v2.w, s00, s11, s22, s01, s02, s12);
}

__global__ __launch_bounds__(BLK) void tp_kernel(const float* __restrict__ in,
                                                 int total_floats,
                                                 float* __restrict__ out) {
    const float4* __restrict__ in4 = (const float4*)in;
    const int num_groups8 = total_floats / 24;   // groups of 8 rows = 6 float4s

    float s00 = 0.f, s11 = 0.f, s22 = 0.f, s01 = 0.f, s02 = 0.f, s12 = 0.f;

    const int tid = threadIdx.x;
    int gidx = blockIdx.x * BLK + tid;
    const int stride = gridDim.x * BLK;

    for (int g = gidx; g < num_groups8; g += stride) {
        const float4* p = in4 + 6 * (size_t)g;
        float4 v0 = __ldcs(p + 0);
        float4 v1 = __ldcs(p + 1);
        float4 v2 = __ldcs(p + 2);
        float4 v3 = __ldcs(p + 3);
        float4 v4 = __ldcs(p + 4);
        float4 v5 = __ldcs(p + 5);
        acc_vec3(v0, v1, v2, s00, s11, s22, s01, s02, s12);
        acc_vec3(v3, v4, v5, s00, s11, s22, s01, s02, s12);
    }

    // warp reduction
    #pragma unroll
    for (int o = 16; o > 0; o >>= 1) {
        s00 += __shfl_down_sync(0xffffffffu, s00, o);
        s11 += __shfl_down_sync(0xffffffffu, s11, o);
        s22 += __shfl_down_sync(0xffffffffu, s22, o);
        s01 += __shfl_down_sync(0xffffffffu, s01, o);
        s02 += __shfl_down_sync(0xffffffffu, s02, o);
        s12 += __shfl_down_sync(0xffffffffu, s12, o);
    }

    __shared__ float sm[NACC][BLK / 32];
    const int lane = tid & 31;
    const int w = tid >> 5;
    if (lane == 0) {
        sm[0][w] = s00; sm[1][w] = s11; sm[2][w] = s22;
        sm[3][w] = s01; sm[4][w] = s02; sm[5][w] = s12;
    }
    __syncthreads();

    // ---- single-publisher: thread 0 folds, writes, fences, counts ----
    __shared__ bool is_last;
    if (tid == 0) {
        float t[NACC];
        #pragma unroll
        for (int k = 0; k < NACC; k++) {
            float acc = 0.f;
            #pragma unroll
            for (int i = 0; i < BLK / 32; i++) acc += sm[k][i];
            t[k] = acc;
        }
        float4* rec = (float4*)&g_part[blockIdx.x * 8];
        rec[0] = make_float4(t[0], t[1], t[2], t[3]);
        rec[1] = make_float4(t[4], t[5], 0.f, 0.f);
        __threadfence();                       // the ONLY gpu-scope fence in the block
        unsigned int prev = atomicAdd(&g_count, 1u);
        is_last = (prev == (unsigned int)(gridDim.x - 1));
    }
    __syncthreads();
    if (!is_last) return;

    // ---- last block: fold all partials (L2-coherent loads, fixed order) ----
    float s[NACC];
    #pragma unroll
    for (int k = 0; k < NACC; k++) s[k] = 0.f;

    for (int b = tid; b < GRID_MAIN; b += BLK) {
        const float4* rec = (const float4*)&g_part[b * 8];
        float4 p0 = __ldcg(rec + 0);
        float4 p1 = __ldcg(rec + 1);
        s[0] += p0.x; s[1] += p0.y; s[2] += p0.z;
        s[3] += p0.w; s[4] += p1.x; s[5] += p1.y;
    }

    // tail rows beyond groups-of-8, distributed over this block (fixed order)
    {
        int num_rows = total_floats / 3;
        int covered = num_groups8 * 8;
        for (int r = covered + tid; r < num_rows; r += BLK) {
            float a = in[3 * r + 0], b = in[3 * r + 1], c = in[3 * r + 2];
            s[0] += a * a; s[1] += b * b; s[2] += c * c;
            s[3] += a * b; s[4] += a * c; s[5] += b * c;
        }
    }

    // block reduce (fixed order -> deterministic)
    #pragma unroll
    for (int o = 16; o > 0; o >>= 1) {
        #pragma unroll
        for (int k = 0; k < NACC; k++) s[k] += __shfl_down_sync(0xffffffffu, s[k], o);
    }
    __shared__ float sm2[NACC][BLK / 32];
    if (lane == 0) {
        #pragma unroll
        for (int k = 0; k < NACC; k++) sm2[k][w] = s[k];
    }
    __syncthreads();

    if (tid == 0) {
        float v[NACC];
        #pragma unroll
        for (int k = 0; k < NACC; k++) {
            v[k] = 0.f;
            #pragma unroll
            for (int i = 0; i < BLK / 32; i++) v[k] += sm2[k][i];
        }
        const float s00f = v[0], s11f = v[1], s22f = v[2];
        const float s01f = v[3], s02f = v[4], s12f = v[5];
        const float INV_SQRT3 = 0.57735026918962576f;
        const float SQRT2     = 1.41421356237309505f;
        const float INV_SQRT6 = 0.40824829046386302f;
        const float INV_SQRT2 = 0.70710678118654752f;

        out[0] = (s00f + s11f + s22f) * INV_SQRT3;        // 0e
        out[1] = 0.f;                                     // 1e: cross(x,x)=0
        out[2] = 0.f;
        out[3] = 0.f;
        out[4] = SQRT2 * s02f;                            // 2e m=-2
        out[5] = SQRT2 * s01f;                            // 2e m=-1
        out[6] = (2.f * s11f - s00f - s22f) * INV_SQRT6;  // 2e m=0
        out[7] = SQRT2 * s12f;                            // 2e m=+1
        out[8] = (s22f - s00f) * INV_SQRT2;               // 2e m=+2

        g_count = 0;   // reset for next graph replay
    }
}

extern "C" void kernel_launch(void* const* d_in, const int* in_sizes, int n_in,
                              void* d_out, int out_size) {
    const float* frac = (const float*)d_in[0];
    float* out = (float*)d_out;
    int total_floats = in_sizes[0];          // N*3

    tp_kernel<<<GRID_MAIN, BLK>>>(frac, total_floats, out);
}

// round 8
// speedup vs baseline: 1.4913x; 1.4175x over previous
#include <cuda_runtime.h>

// SimpleTP: FullTensorProduct('1x1o','1x1o') of frac with itself, summed over N.
// = 6 quadratic moments s_ij = sum_n a_i a_j, then a fixed 9-output linear map.
//
// Warp-cooperative dense streaming: each warp owns a contiguous 768-float region
// (256 rows). Each lane loads 6 lane-contiguous float4s (dense LDG.128, 4
// wavefronts each). Role rotation handled algebraically: element e of float4
// (32k+lane) has role m=(2k+lane+e)%3; accumulate into local buckets
// r'=(2k+e)%3 (compile-time), rotate by lane%3 once at the end.
// Cross-float4 products use the successor lane's leading pair via shuffles.

#define BLK 256
#define GRID_MAIN 592            // 148 SMs * 4 blocks (launch_bounds 256,4)
#define NACC 6
#define FULLMASK 0xffffffffu

__device__ float g_part[NACC * GRID_MAIN];

// Per-float4 products. q-rotated bucket refs passed explicitly:
//  e=0..3 target buckets r' = q, q+1, q+2, q (mod 3).
//  d=0: squares; d=1: dist-1 pairs (incl. u.w*s0); d=2: dist-2 (incl. u.z*s0, u.w*s1)
#define PROC_K(u, s0, s1, B0q, B0q1, B0q2, B1q, B1q1, B1q2, B2q, B2q1, B2q2) \
    do {                                                                     \
        B0q  = fmaf(u.x, u.x, B0q);                                          \
        B0q1 = fmaf(u.y, u.y, B0q1);                                         \
        B0q2 = fmaf(u.z, u.z, B0q2);                                         \
        B0q  = fmaf(u.w, u.w, B0q);                                          \
        B1q  = fmaf(u.x, u.y, B1q);                                          \
        B1q1 = fmaf(u.y, u.z, B1q1);                                         \
        B1q2 = fmaf(u.z, u.w, B1q2);                                         \
        B1q  = fmaf(u.w, s0,  B1q);                                          \
        B2q  = fmaf(u.x, u.z, B2q);                                          \
        B2q1 = fmaf(u.y, u.w, B2q1);                                         \
        B2q2 = fmaf(u.z, s0,  B2q2);                                         \
        B2q  = fmaf(u.w, s1,  B2q);                                          \
    } while (0)

// successor pair for k<5: shfl_down(1), lane31 patched from (k+1, lane0)
#define SUCC(uk, uk1, s0, s1)                                  \
    do {                                                       \
        s0 = __shfl_down_sync(FULLMASK, uk.x, 1);              \
        s1 = __shfl_down_sync(FULLMASK, uk.y, 1);              \
        float _b0 = __shfl_sync(FULLMASK, uk1.x, 0);           \
        float _b1 = __shfl_sync(FULLMASK, uk1.y, 0);           \
        if (lane == 31) { s0 = _b0; s1 = _b1; }                \
    } while (0)

__global__ __launch_bounds__(BLK, 4) void tp_moments_kernel(const float4* __restrict__ in4,
                                                            int num_regions) {
    const int lane = threadIdx.x & 31;
    const int gwarp = blockIdx.x * (BLK / 32) + (threadIdx.x >> 5);
    const int nwarps = gridDim.x * (BLK / 32);

    // B[d][r'] local buckets
    float B00 = 0.f, B01 = 0.f, B02 = 0.f;
    float B10 = 0.f, B11 = 0.f, B12 = 0.f;
    float B20 = 0.f, B21 = 0.f, B22 = 0.f;

    for (int R = gwarp; R < num_regions; R += nwarps) {
        const float4* base = in4 + (size_t)R * 192 + lane;
        float4 u0 = base[0];
        float4 u1 = base[32];
        float4 u2 = base[64];
        float4 u3 = base[96];
        float4 u4 = base[128];
        float4 u5 = base[160];

        float s0, s1;
        // k=0, q=0
        SUCC(u0, u1, s0, s1);
        PROC_K(u0, s0, s1, B00, B01, B02, B10, B11, B12, B20, B21, B22);
        // k=1, q=2  (buckets rotate: q,q1,q2 = 2,0,1)
        SUCC(u1, u2, s0, s1);
        PROC_K(u1, s0, s1, B02, B00, B01, B12, B10, B11, B22, B20, B21);
        // k=2, q=1
        SUCC(u2, u3, s0, s1);
        PROC_K(u2, s0, s1, B01, B02, B00, B11, B12, B10, B21, B22, B20);
        // k=3, q=0
        SUCC(u3, u4, s0, s1);
        PROC_K(u3, s0, s1, B00, B01, B02, B10, B11, B12, B20, B21, B22);
        // k=4, q=2
        SUCC(u4, u5, s0, s1);
        PROC_K(u4, s0, s1, B02, B00, B01, B12, B10, B11, B22, B20, B21);
        // k=5, q=1: lane31's succ = its own pair -> products land in junk buckets
        s0 = __shfl_down_sync(FULLMASK, u5.x, 1);
        s1 = __shfl_down_sync(FULLMASK, u5.y, 1);
        PROC_K(u5, s0, s1, B01, B02, B00, B11, B12, B10, B21, B22, B20);
    }

    // rotate local buckets to global moments: global m = (r' + lane) mod 3
    // valid set: s00=(m0,d0) s11=(m1,d0) s22=(m2,d0) s01=(m0,d1) s12=(m1,d1) s02=(m0,d2)
    int c = lane % 3;
    float s00, s11, s22, s01, s12, s02;
    if (c == 0)      { s00 = B00; s11 = B01; s22 = B02; s01 = B10; s12 = B11; s02 = B20; }
    else if (c == 1) { s00 = B02; s11 = B00; s22 = B01; s01 = B12; s12 = B10; s02 = B22; }
    else             { s00 = B01; s11 = B02; s22 = B00; s01 = B11; s12 = B12; s02 = B21; }

    // warp reduction
    #pragma unroll
    for (int o = 16; o > 0; o >>= 1) {
        s00 += __shfl_down_sync(FULLMASK, s00, o);
        s11 += __shfl_down_sync(FULLMASK, s11, o);
        s22 += __shfl_down_sync(FULLMASK, s22, o);
        s01 += __shfl_down_sync(FULLMASK, s01, o);
        s02 += __shfl_down_sync(FULLMASK, s02, o);
        s12 += __shfl_down_sync(FULLMASK, s12, o);
    }

    __shared__ float sm[NACC][BLK / 32];
    int w = threadIdx.x >> 5;
    if (lane == 0) {
        sm[0][w] = s00; sm[1][w] = s11; sm[2][w] = s22;
        sm[3][w] = s01; sm[4][w] = s02; sm[5][w] = s12;
    }
    __syncthreads();

    if (threadIdx.x < NACC) {
        float t = 0.f;
        #pragma unroll
        for (int i = 0; i < BLK / 32; i++) t += sm[threadIdx.x][i];
        g_part[threadIdx.x * GRID_MAIN + blockIdx.x] = t;
    }
}

__global__ __launch_bounds__(BLK) void tp_finalize_kernel(const float* __restrict__ in,
                                                          int total_floats,
                                                          int num_regions,
                                                          float* __restrict__ out) {
    float s[NACC];
    #pragma unroll
    for (int k = 0; k < NACC; k++) s[k] = 0.f;

    for (int b = threadIdx.x; b < GRID_MAIN; b += BLK) {
        #pragma unroll
        for (int k = 0; k < NACC; k++) s[k] += g_part[k * GRID_MAIN + b];
    }

    // tail rows beyond full regions, distributed (fixed order per thread)
    {
        int num_rows = total_floats / 3;
        int covered = num_regions * 256;
        for (int r = covered + threadIdx.x; r < num_rows; r += BLK) {
            float a = in[3 * r + 0], b = in[3 * r + 1], c = in[3 * r + 2];
            s[0] += a * a; s[1] += b * b; s[2] += c * c;
            s[3] += a * b; s[4] += a * c; s[5] += b * c;
        }
    }

    #pragma unroll
    for (int o = 16; o > 0; o >>= 1) {
        #pragma unroll
        for (int k = 0; k < NACC; k++) s[k] += __shfl_down_sync(FULLMASK, s[k], o);
    }
    __shared__ float sm[NACC][BLK / 32];
    int lane = threadIdx.x & 31;
    int w = threadIdx.x >> 5;
    if (lane == 0) {
        #pragma unroll
        for (int k = 0; k < NACC; k++) sm[k][w] = s[k];
    }
    __syncthreads();

    if (threadIdx.x == 0) {
        float t[NACC];
        #pragma unroll
        for (int k = 0; k < NACC; k++) {
            t[k] = 0.f;
            #pragma unroll
            for (int i = 0; i < BLK / 32; i++) t[k] += sm[k][i];
        }
        const float s00f = t[0], s11f = t[1], s22f = t[2];
        const float s01f = t[3], s02f = t[4], s12f = t[5];
        const float INV_SQRT3 = 0.57735026918962576f;
        const float SQRT2     = 1.41421356237309505f;
        const float INV_SQRT6 = 0.40824829046386302f;
        const float INV_SQRT2 = 0.70710678118654752f;

        out[0] = (s00f + s11f + s22f) * INV_SQRT3;        // 0e
        out[1] = 0.f;                                     // 1e: cross(x,x)=0
        out[2] = 0.f;
        out[3] = 0.f;
        out[4] = SQRT2 * s02f;                            // 2e m=-2
        out[5] = SQRT2 * s01f;                            // 2e m=-1
        out[6] = (2.f * s11f - s00f - s22f) * INV_SQRT6;  // 2e m=0
        out[7] = SQRT2 * s12f;                            // 2e m=+1
        out[8] = (s22f - s00f) * INV_SQRT2;               // 2e m=+2
    }
}

extern "C" void kernel_launch(void* const* d_in, const int* in_sizes, int n_in,
                              void* d_out, int out_size) {
    const float* frac = (const float*)d_in[0];
    float* out = (float*)d_out;
    int total_floats = in_sizes[0];              // N*3
    int num_regions = total_floats / 768;        // 768 floats = 256 rows per warp-region

    tp_moments_kernel<<<GRID_MAIN, BLK>>>((const float4*)frac, num_regions);
    tp_finalize_kernel<<<1, BLK>>>(frac, total_floats, num_regions, out);
}